// round 1
// baseline (speedup 1.0000x reference)
#include <cuda_runtime.h>
#include <math.h>

#define BATCH 8
#define CHN 512
#define NPIX 4096
#define GROUPS 32
#define CPG 16   // CHN/GROUPS

// Scratch (allocation-free rule: __device__ globals)
__device__ float g_h[(size_t)BATCH*CHN*NPIX];
__device__ float g_q[(size_t)BATCH*CHN*NPIX];
__device__ float g_k[(size_t)BATCH*CHN*NPIX];
__device__ float g_v[(size_t)BATCH*CHN*NPIX];
__device__ float g_o[(size_t)BATCH*CHN*NPIX];
__device__ float g_attn[(size_t)BATCH*NPIX*NPIX];   // 512 MB

// ---------------- GroupNorm ----------------
// one block per (batch, group); group = 16 channels x 4096 pixels = 65536 floats
__global__ void gn_kernel(const float* __restrict__ x,
                          const float* __restrict__ w,
                          const float* __restrict__ b) {
    int batch = blockIdx.x / GROUPS;
    int grp   = blockIdx.x % GROUPS;
    size_t base = ((size_t)batch*CHN + (size_t)grp*CPG) * NPIX;
    const float* xp = x + base;
    float* hp = g_h + base;
    const int GE = CPG * NPIX;

    float s = 0.f, ss = 0.f;
    for (int i = threadIdx.x; i < GE; i += blockDim.x) {
        float v = xp[i];
        s += v; ss += v*v;
    }
    __shared__ float r1[256], r2[256];
    r1[threadIdx.x] = s; r2[threadIdx.x] = ss;
    __syncthreads();
    for (int st = 128; st > 0; st >>= 1) {
        if (threadIdx.x < st) {
            r1[threadIdx.x] += r1[threadIdx.x + st];
            r2[threadIdx.x] += r2[threadIdx.x + st];
        }
        __syncthreads();
    }
    float mean = r1[0] / (float)GE;
    float var  = r2[0] / (float)GE - mean*mean;
    float rstd = rsqrtf(var + 1e-6f);

    for (int i = threadIdx.x; i < GE; i += blockDim.x) {
        int ch = grp*CPG + (i >> 12);   // i / NPIX
        hp[i] = (xp[i] - mean) * rstd * w[ch] + b[ch];
    }
}

// ---------------- Tiled GEMM config ----------------
#define BM 64
#define BN 64
#define BK 16

// conv1x1: out[b,m,n] = sum_k W[m,k]*in[b,k,n] + bias[m] (+ residual[b,m,n])
__global__ void conv_kernel(const float* __restrict__ W,
                            const float* __restrict__ bias,
                            const float* __restrict__ in,
                            const float* __restrict__ residual,
                            float* __restrict__ out) {
    __shared__ float As[BK][BM];
    __shared__ float Bs[BK][BN];
    int b  = blockIdx.z;
    int m0 = blockIdx.y * BM;
    int n0 = blockIdx.x * BN;
    const float* inb = in + (size_t)b*CHN*NPIX;
    int tid = threadIdx.x;
    int tx = tid & 15, ty = tid >> 4;

    float acc[4][4] = {};
    for (int k0 = 0; k0 < CHN; k0 += BK) {
        {   // A tile: W rows m0..m0+63, cols k0..k0+15
            int kq = (tid & 3) * 4;
            int m  = tid >> 2;
            float4 a4 = *reinterpret_cast<const float4*>(W + (size_t)(m0+m)*CHN + k0 + kq);
            As[kq+0][m] = a4.x; As[kq+1][m] = a4.y; As[kq+2][m] = a4.z; As[kq+3][m] = a4.w;
        }
        {   // B tile: in rows k0..k0+15, cols n0..n0+63
            int nq = (tid & 15) * 4;
            int k  = tid >> 4;
            float4 b4 = *reinterpret_cast<const float4*>(inb + (size_t)(k0+k)*NPIX + n0 + nq);
            *reinterpret_cast<float4*>(&Bs[k][nq]) = b4;
        }
        __syncthreads();
        #pragma unroll
        for (int kk = 0; kk < BK; kk++) {
            float a[4], bv[4];
            #pragma unroll
            for (int i = 0; i < 4; i++) a[i] = As[kk][ty*4 + i];
            #pragma unroll
            for (int j = 0; j < 4; j++) bv[j] = Bs[kk][tx*4 + j];
            #pragma unroll
            for (int i = 0; i < 4; i++)
                #pragma unroll
                for (int j = 0; j < 4; j++)
                    acc[i][j] += a[i] * bv[j];
        }
        __syncthreads();
    }
    #pragma unroll
    for (int i = 0; i < 4; i++) {
        int m = m0 + ty*4 + i;
        float bi = bias[m];
        #pragma unroll
        for (int j = 0; j < 4; j++) {
            int n = n0 + tx*4 + j;
            size_t idx = ((size_t)b*CHN + m)*NPIX + n;
            float v = acc[i][j] + bi;
            if (residual) v += residual[idx];
            out[idx] = v;
        }
    }
}

// logits: attn[b,i,j] = scale * sum_c q[b,c,i]*k[b,c,j]
__global__ void logits_kernel(const float* __restrict__ q,
                              const float* __restrict__ kmat) {
    __shared__ float As[BK][BM];
    __shared__ float Bs[BK][BN];
    int b  = blockIdx.z;
    int m0 = blockIdx.y * BM;   // i
    int n0 = blockIdx.x * BN;   // j
    const float* qb = q    + (size_t)b*CHN*NPIX;
    const float* kb = kmat + (size_t)b*CHN*NPIX;
    int tid = threadIdx.x;
    int tx = tid & 15, ty = tid >> 4;

    float acc[4][4] = {};
    for (int k0 = 0; k0 < CHN; k0 += BK) {
        int mq = (tid & 15) * 4;
        int kr = tid >> 4;
        float4 a4 = *reinterpret_cast<const float4*>(qb + (size_t)(k0+kr)*NPIX + m0 + mq);
        *reinterpret_cast<float4*>(&As[kr][mq]) = a4;
        float4 b4 = *reinterpret_cast<const float4*>(kb + (size_t)(k0+kr)*NPIX + n0 + mq);
        *reinterpret_cast<float4*>(&Bs[kr][mq]) = b4;
        __syncthreads();
        #pragma unroll
        for (int kk = 0; kk < BK; kk++) {
            float a[4], bv[4];
            #pragma unroll
            for (int i = 0; i < 4; i++) a[i] = As[kk][ty*4 + i];
            #pragma unroll
            for (int j = 0; j < 4; j++) bv[j] = Bs[kk][tx*4 + j];
            #pragma unroll
            for (int i = 0; i < 4; i++)
                #pragma unroll
                for (int j = 0; j < 4; j++)
                    acc[i][j] += a[i] * bv[j];
        }
        __syncthreads();
    }
    const float scale = 0.044194173824159216f;   // 512^-0.5
    #pragma unroll
    for (int i = 0; i < 4; i++) {
        int m = m0 + ty*4 + i;
        #pragma unroll
        for (int j = 0; j < 4; j++) {
            int n = n0 + tx*4 + j;
            g_attn[((size_t)b*NPIX + m)*NPIX + n] = acc[i][j] * scale;
        }
    }
}

// softmax over last dim; one block per row
__global__ void softmax_kernel() {
    float* row = g_attn + (size_t)blockIdx.x * NPIX;
    __shared__ float buf[NPIX];
    __shared__ float red[256];
    int tid = threadIdx.x;

    float m = -1e30f;
    for (int i = tid; i < NPIX; i += 256) {
        float v = row[i];
        buf[i] = v;
        m = fmaxf(m, v);
    }
    red[tid] = m; __syncthreads();
    for (int st = 128; st > 0; st >>= 1) {
        if (tid < st) red[tid] = fmaxf(red[tid], red[tid + st]);
        __syncthreads();
    }
    float mx = red[0];
    __syncthreads();

    float s = 0.f;
    for (int i = tid; i < NPIX; i += 256) {
        float e = __expf(buf[i] - mx);
        buf[i] = e;
        s += e;
    }
    red[tid] = s; __syncthreads();
    for (int st = 128; st > 0; st >>= 1) {
        if (tid < st) red[tid] += red[tid + st];
        __syncthreads();
    }
    float inv = 1.0f / red[0];
    for (int i = tid; i < NPIX; i += 256) row[i] = buf[i] * inv;
}

// o[b,c,i] = sum_j v[b,c,j]*attn[b,i,j]   (M=c=512, N=i=4096, K=j=4096)
__global__ void out_kernel(const float* __restrict__ v) {
    __shared__ float As[BK][BM];
    __shared__ float Bs[BK][BN];
    int b  = blockIdx.z;
    int m0 = blockIdx.y * BM;   // c
    int n0 = blockIdx.x * BN;   // i
    const float* vb = v      + (size_t)b*CHN*NPIX;
    const float* ab = g_attn + (size_t)b*NPIX*NPIX;
    int tid = threadIdx.x;
    int tx = tid & 15, ty = tid >> 4;

    float acc[4][4] = {};
    for (int k0 = 0; k0 < NPIX; k0 += BK) {
        int kq = (tid & 3) * 4;
        int r  = tid >> 2;
        float4 a4 = *reinterpret_cast<const float4*>(vb + (size_t)(m0+r)*NPIX + k0 + kq);
        As[kq+0][r] = a4.x; As[kq+1][r] = a4.y; As[kq+2][r] = a4.z; As[kq+3][r] = a4.w;
        float4 b4 = *reinterpret_cast<const float4*>(ab + (size_t)(n0+r)*NPIX + k0 + kq);
        Bs[kq+0][r] = b4.x; Bs[kq+1][r] = b4.y; Bs[kq+2][r] = b4.z; Bs[kq+3][r] = b4.w;
        __syncthreads();
        #pragma unroll
        for (int kk = 0; kk < BK; kk++) {
            float a[4], bv[4];
            #pragma unroll
            for (int i = 0; i < 4; i++) a[i] = As[kk][ty*4 + i];
            #pragma unroll
            for (int j = 0; j < 4; j++) bv[j] = Bs[kk][tx*4 + j];
            #pragma unroll
            for (int i = 0; i < 4; i++)
                #pragma unroll
                for (int j = 0; j < 4; j++)
                    acc[i][j] += a[i] * bv[j];
        }
        __syncthreads();
    }
    #pragma unroll
    for (int i = 0; i < 4; i++) {
        int m = m0 + ty*4 + i;
        #pragma unroll
        for (int j = 0; j < 4; j++) {
            int n = n0 + tx*4 + j;
            g_o[((size_t)b*CHN + m)*NPIX + n] = acc[i][j];
        }
    }
}

extern "C" void kernel_launch(void* const* d_in, const int* in_sizes, int n_in,
                              void* d_out, int out_size) {
    const float* x    = (const float*)d_in[0];
    const float* gn_w = (const float*)d_in[1];
    const float* gn_b = (const float*)d_in[2];
    const float* q_w  = (const float*)d_in[3];
    const float* q_b  = (const float*)d_in[4];
    const float* k_w  = (const float*)d_in[5];
    const float* k_b  = (const float*)d_in[6];
    const float* v_w  = (const float*)d_in[7];
    const float* v_b  = (const float*)d_in[8];
    const float* p_w  = (const float*)d_in[9];
    const float* p_b  = (const float*)d_in[10];
    float* out = (float*)d_out;

    float *h, *q, *k, *v, *o;
    cudaGetSymbolAddress((void**)&h, g_h);
    cudaGetSymbolAddress((void**)&q, g_q);
    cudaGetSymbolAddress((void**)&k, g_k);
    cudaGetSymbolAddress((void**)&v, g_v);
    cudaGetSymbolAddress((void**)&o, g_o);

    // 1. GroupNorm
    gn_kernel<<<BATCH*GROUPS, 256>>>(x, gn_w, gn_b);

    // 2. q, k, v projections (M=512, N=4096, K=512 per batch)
    dim3 cgrid(NPIX/BN, CHN/BM, BATCH);
    conv_kernel<<<cgrid, 256>>>(q_w, q_b, h, nullptr, q);
    conv_kernel<<<cgrid, 256>>>(k_w, k_b, h, nullptr, k);
    conv_kernel<<<cgrid, 256>>>(v_w, v_b, h, nullptr, v);

    // 3. attention logits (4096x4096, K=512 per batch)
    dim3 lgrid(NPIX/BN, NPIX/BM, BATCH);
    logits_kernel<<<lgrid, 256>>>(q, k);

    // 4. softmax rows
    softmax_kernel<<<BATCH*NPIX, 256>>>();

    // 5. o = v @ attn^T (M=512, N=4096, K=4096 per batch)
    dim3 ogrid(NPIX/BN, CHN/BM, BATCH);
    out_kernel<<<ogrid, 256>>>(v);

    // 6. proj conv1x1 + residual -> d_out
    conv_kernel<<<cgrid, 256>>>(p_w, p_b, o, x, out);
}

// round 2
// speedup vs baseline: 6.1306x; 6.1306x over previous
#include <cuda_runtime.h>
#include <cuda_bf16.h>
#include <math.h>

#define BATCH 8
#define CHN 512
#define NPIX 4096
#define GROUPS 32
#define CPG 16

// ---------------- scratch (__device__ globals; no allocation allowed) -------
__device__ __nv_bfloat16 g_ht[(size_t)BATCH*NPIX*CHN];     // h^T  [b][n][c]
__device__ __nv_bfloat16 g_qt[(size_t)BATCH*NPIX*CHN];     // q^T  [b][i][c]
__device__ __nv_bfloat16 g_kt[(size_t)BATCH*NPIX*CHN];     // k^T  [b][j][c]
__device__ __nv_bfloat16 g_v [(size_t)BATCH*CHN*NPIX];     // v    [b][c][j]
__device__ __nv_bfloat16 g_ot[(size_t)BATCH*NPIX*CHN];     // o^T  [b][i][c]
__device__ __nv_bfloat16 g_attn[(size_t)BATCH*NPIX*NPIX];  // attn [b][i][j] 256MB
__device__ __nv_bfloat16 g_wq[CHN*CHN];
__device__ __nv_bfloat16 g_wk[CHN*CHN];
__device__ __nv_bfloat16 g_wv[CHN*CHN];
__device__ __nv_bfloat16 g_wp[CHN*CHN];

// ---------------- fp32 -> bf16 weight convert -------------------------------
__global__ void cvt_kernel(const float* __restrict__ s, __nv_bfloat16* __restrict__ d, int n) {
    int i = blockIdx.x * blockDim.x + threadIdx.x;
    if (i < n) d[i] = __float2bfloat16(s[i]);
}

// ---------------- GroupNorm -> h^T bf16 --------------------------------------
// one block per (batch, group)
__global__ void gn_kernel(const float* __restrict__ x,
                          const float* __restrict__ w,
                          const float* __restrict__ b,
                          __nv_bfloat16* __restrict__ ht) {
    int batch = blockIdx.x >> 5;
    int grp   = blockIdx.x & 31;
    const float* xp = x + ((size_t)batch*CHN + (size_t)grp*CPG) * NPIX;
    const int GE = CPG * NPIX;
    int tid = threadIdx.x;

    float s = 0.f, ss = 0.f;
    for (int i = tid; i < GE; i += 256) {
        float v = xp[i];
        s += v; ss += v*v;
    }
    __shared__ float r1[256], r2[256];
    r1[tid] = s; r2[tid] = ss;
    __syncthreads();
    for (int st = 128; st > 0; st >>= 1) {
        if (tid < st) { r1[tid] += r1[tid+st]; r2[tid] += r2[tid+st]; }
        __syncthreads();
    }
    float mean = r1[0] / (float)GE;
    float var  = r2[0] / (float)GE - mean*mean;
    float rstd = rsqrtf(var + 1e-6f);

    float wl[CPG], bl[CPG];
    #pragma unroll
    for (int c = 0; c < CPG; c++) { wl[c] = w[grp*CPG+c]; bl[c] = b[grp*CPG+c]; }

    for (int n = tid; n < NPIX; n += 256) {
        union { __nv_bfloat16 v[CPG]; uint4 u[2]; } pk;
        #pragma unroll
        for (int c = 0; c < CPG; c++) {
            float xv = xp[(size_t)c*NPIX + n];
            pk.v[c] = __float2bfloat16((xv - mean) * rstd * wl[c] + bl[c]);
        }
        uint4* dst = reinterpret_cast<uint4*>(ht + ((size_t)batch*NPIX + n)*CHN + grp*CPG);
        dst[0] = pk.u[0]; dst[1] = pk.u[1];
    }
}

// ---------------- unified bf16 tensor-core GEMM ------------------------------
// C[m][n] = sum_k A[m][k] * B[n][k]  (both operands k-contiguous)
// EPI: 0 = +bias, write bf16 transposed Ct[n*M+m]      (q/k conv)
//      1 = +bias, write bf16 normal   C [m*N+n]        (v conv)
//      2 = *scale, write bf16 normal                   (logits)
//      3 = write bf16 transposed                       (attn @ V)
//      4 = +bias +residual, write fp32 normal          (proj)
#define BM 128
#define BN 128
#define BK 32
#define SST 40   // BK + 8 skew (conflict-free frag loads)

__device__ __forceinline__ void cpa16(void* smem, const void* g) {
    unsigned s = (unsigned)__cvta_generic_to_shared(smem);
    asm volatile("cp.async.cg.shared.global [%0], [%1], 16;" :: "r"(s), "l"(g) : "memory");
}
__device__ __forceinline__ void cpa_commit() {
    asm volatile("cp.async.commit_group;" ::: "memory");
}
template<int N_> __device__ __forceinline__ void cpa_wait() {
    asm volatile("cp.async.wait_group %0;" :: "n"(N_) : "memory");
}

template<int EPI>
__global__ void __launch_bounds__(256)
gemm_kernel(const __nv_bfloat16* __restrict__ A, size_t sA,
            const __nv_bfloat16* __restrict__ B, size_t sB,
            void* __restrict__ Cv, size_t sC,
            const float* __restrict__ bias,
            const float* __restrict__ resid,
            int M, int N, int K, float scale) {
    __shared__ __nv_bfloat16 As[2][BM][SST];
    __shared__ __nv_bfloat16 Bs[2][BN][SST];

    int b  = blockIdx.z;
    int m0 = blockIdx.y * BM;
    int n0 = blockIdx.x * BN;
    const __nv_bfloat16* Ab = A + (size_t)b * sA;
    const __nv_bfloat16* Bb = B + (size_t)b * sB;

    int tid  = threadIdx.x;
    int wid  = tid >> 5;
    int lane = tid & 31;
    int wm = wid & 3;        // 4 warps along M -> 32 rows each
    int wn = wid >> 2;       // 2 warps along N -> 64 cols each
    int g  = lane >> 2;
    int t  = lane & 3;

    float acc[2][8][4];
    #pragma unroll
    for (int i = 0; i < 2; i++)
        #pragma unroll
        for (int j = 0; j < 8; j++)
            #pragma unroll
            for (int r = 0; r < 4; r++) acc[i][j][r] = 0.f;

    // tile copy: 512 16B-chunks per operand, 2 per thread
    int r0 = tid >> 2, c0 = (tid & 3) * 8;
    int r1 = r0 + 64;

    auto copy_stage = [&](int buf, int k0) {
        cpa16(&As[buf][r0][c0], Ab + (size_t)(m0 + r0)*K + k0 + c0);
        cpa16(&As[buf][r1][c0], Ab + (size_t)(m0 + r1)*K + k0 + c0);
        cpa16(&Bs[buf][r0][c0], Bb + (size_t)(n0 + r0)*K + k0 + c0);
        cpa16(&Bs[buf][r1][c0], Bb + (size_t)(n0 + r1)*K + k0 + c0);
        cpa_commit();
    };

    int ntiles = K / BK;
    copy_stage(0, 0);

    for (int kt = 0; kt < ntiles; kt++) {
        if (kt + 1 < ntiles) { copy_stage((kt+1)&1, (kt+1)*BK); cpa_wait<1>(); }
        else                 { cpa_wait<0>(); }
        __syncthreads();

        int s = kt & 1;
        #pragma unroll
        for (int ks = 0; ks < 2; ks++) {
            int kb = ks * 16;
            unsigned af[2][4], bf[8][2];
            #pragma unroll
            for (int am = 0; am < 2; am++) {
                int rb = wm*32 + am*16;
                af[am][0] = *reinterpret_cast<const unsigned*>(&As[s][rb + g    ][kb + 2*t]);
                af[am][1] = *reinterpret_cast<const unsigned*>(&As[s][rb + g + 8][kb + 2*t]);
                af[am][2] = *reinterpret_cast<const unsigned*>(&As[s][rb + g    ][kb + 2*t + 8]);
                af[am][3] = *reinterpret_cast<const unsigned*>(&As[s][rb + g + 8][kb + 2*t + 8]);
            }
            #pragma unroll
            for (int an = 0; an < 8; an++) {
                int nb = wn*64 + an*8;
                bf[an][0] = *reinterpret_cast<const unsigned*>(&Bs[s][nb + g][kb + 2*t]);
                bf[an][1] = *reinterpret_cast<const unsigned*>(&Bs[s][nb + g][kb + 2*t + 8]);
            }
            #pragma unroll
            for (int am = 0; am < 2; am++)
                #pragma unroll
                for (int an = 0; an < 8; an++) {
                    float* c = acc[am][an];
                    asm volatile(
                        "mma.sync.aligned.m16n8k16.row.col.f32.bf16.bf16.f32 "
                        "{%0,%1,%2,%3}, {%4,%5,%6,%7}, {%8,%9}, {%0,%1,%2,%3};"
                        : "+f"(c[0]), "+f"(c[1]), "+f"(c[2]), "+f"(c[3])
                        : "r"(af[am][0]), "r"(af[am][1]), "r"(af[am][2]), "r"(af[am][3]),
                          "r"(bf[an][0]), "r"(bf[an][1]));
                }
        }
        __syncthreads();
    }

    // ------------- epilogue -------------
    #pragma unroll
    for (int am = 0; am < 2; am++) {
        #pragma unroll
        for (int an = 0; an < 8; an++) {
            int ml = m0 + wm*32 + am*16 + g;
            int mh = ml + 8;
            int ne = n0 + wn*64 + an*8 + 2*t;
            float v0 = acc[am][an][0], v1 = acc[am][an][1];
            float v2 = acc[am][an][2], v3 = acc[am][an][3];

            if (EPI == 0) {  // bias + bf16 transposed
                __nv_bfloat16* C = (__nv_bfloat16*)Cv + (size_t)b*sC;
                float bl = bias[ml], bh = bias[mh];
                C[(size_t)(ne  )*M + ml] = __float2bfloat16(v0 + bl);
                C[(size_t)(ne+1)*M + ml] = __float2bfloat16(v1 + bl);
                C[(size_t)(ne  )*M + mh] = __float2bfloat16(v2 + bh);
                C[(size_t)(ne+1)*M + mh] = __float2bfloat16(v3 + bh);
            } else if (EPI == 1) {  // bias + bf16 normal
                __nv_bfloat16* C = (__nv_bfloat16*)Cv + (size_t)b*sC;
                float bl = bias[ml], bh = bias[mh];
                __nv_bfloat162 p0{__float2bfloat16(v0 + bl), __float2bfloat16(v1 + bl)};
                __nv_bfloat162 p1{__float2bfloat16(v2 + bh), __float2bfloat16(v3 + bh)};
                *reinterpret_cast<__nv_bfloat162*>(C + (size_t)ml*N + ne) = p0;
                *reinterpret_cast<__nv_bfloat162*>(C + (size_t)mh*N + ne) = p1;
            } else if (EPI == 2) {  // scale + bf16 normal
                __nv_bfloat16* C = (__nv_bfloat16*)Cv + (size_t)b*sC;
                __nv_bfloat162 p0{__float2bfloat16(v0*scale), __float2bfloat16(v1*scale)};
                __nv_bfloat162 p1{__float2bfloat16(v2*scale), __float2bfloat16(v3*scale)};
                *reinterpret_cast<__nv_bfloat162*>(C + (size_t)ml*N + ne) = p0;
                *reinterpret_cast<__nv_bfloat162*>(C + (size_t)mh*N + ne) = p1;
            } else if (EPI == 3) {  // bf16 transposed
                __nv_bfloat16* C = (__nv_bfloat16*)Cv + (size_t)b*sC;
                C[(size_t)(ne  )*M + ml] = __float2bfloat16(v0);
                C[(size_t)(ne+1)*M + ml] = __float2bfloat16(v1);
                C[(size_t)(ne  )*M + mh] = __float2bfloat16(v2);
                C[(size_t)(ne+1)*M + mh] = __float2bfloat16(v3);
            } else {  // EPI 4: bias + residual + fp32 normal
                float* C = (float*)Cv + (size_t)b*sC;
                const float* R = resid + (size_t)b*(size_t)M*N;
                float bl = bias[ml], bh = bias[mh];
                float2 rl = *reinterpret_cast<const float2*>(R + (size_t)ml*N + ne);
                float2 rh = *reinterpret_cast<const float2*>(R + (size_t)mh*N + ne);
                float2 o0{v0 + bl + rl.x, v1 + bl + rl.y};
                float2 o1{v2 + bh + rh.x, v3 + bh + rh.y};
                *reinterpret_cast<float2*>(C + (size_t)ml*N + ne) = o0;
                *reinterpret_cast<float2*>(C + (size_t)mh*N + ne) = o1;
            }
        }
    }
}

// ---------------- row softmax, bf16 in-place ---------------------------------
__global__ void softmax_kernel(__nv_bfloat16* __restrict__ attn) {
    __nv_bfloat16* p = attn + (size_t)blockIdx.x * NPIX;
    __shared__ float buf[NPIX];
    __shared__ float red[8];
    int tid = threadIdx.x, lane = tid & 31, wid = tid >> 5;

    float mx = -1e30f;
    for (int i = tid; i < NPIX/8; i += 256) {
        uint4 raw = reinterpret_cast<const uint4*>(p)[i];
        const __nv_bfloat162* h2 = reinterpret_cast<const __nv_bfloat162*>(&raw);
        #pragma unroll
        for (int j = 0; j < 4; j++) {
            float2 f = __bfloat1622float2(h2[j]);
            buf[i*8 + 2*j]   = f.x;
            buf[i*8 + 2*j+1] = f.y;
            mx = fmaxf(mx, fmaxf(f.x, f.y));
        }
    }
    #pragma unroll
    for (int o = 16; o > 0; o >>= 1) mx = fmaxf(mx, __shfl_xor_sync(0xffffffffu, mx, o));
    if (lane == 0) red[wid] = mx;
    __syncthreads();
    if (tid == 0) {
        float m = red[0];
        #pragma unroll
        for (int i = 1; i < 8; i++) m = fmaxf(m, red[i]);
        red[0] = m;
    }
    __syncthreads();
    mx = red[0];
    __syncthreads();

    float s = 0.f;
    for (int i = tid; i < NPIX; i += 256) {
        float e = __expf(buf[i] - mx);
        buf[i] = e;
        s += e;
    }
    #pragma unroll
    for (int o = 16; o > 0; o >>= 1) s += __shfl_xor_sync(0xffffffffu, s, o);
    if (lane == 0) red[wid] = s;
    __syncthreads();
    if (tid == 0) {
        float m = 0.f;
        #pragma unroll
        for (int i = 0; i < 8; i++) m += red[i];
        red[0] = m;
    }
    __syncthreads();
    float inv = 1.0f / red[0];

    for (int i = tid; i < NPIX/8; i += 256) {
        uint4 raw;
        __nv_bfloat162* h2 = reinterpret_cast<__nv_bfloat162*>(&raw);
        #pragma unroll
        for (int j = 0; j < 4; j++) {
            h2[j] = __nv_bfloat162{__float2bfloat16(buf[i*8+2*j]   * inv),
                                   __float2bfloat16(buf[i*8+2*j+1] * inv)};
        }
        reinterpret_cast<uint4*>(p)[i] = raw;
    }
}

// ---------------- launch ------------------------------------------------------
extern "C" void kernel_launch(void* const* d_in, const int* in_sizes, int n_in,
                              void* d_out, int out_size) {
    const float* x    = (const float*)d_in[0];
    const float* gn_w = (const float*)d_in[1];
    const float* gn_b = (const float*)d_in[2];
    const float* q_w  = (const float*)d_in[3];
    const float* q_b  = (const float*)d_in[4];
    const float* k_w  = (const float*)d_in[5];
    const float* k_b  = (const float*)d_in[6];
    const float* v_w  = (const float*)d_in[7];
    const float* v_b  = (const float*)d_in[8];
    const float* p_w  = (const float*)d_in[9];
    const float* p_b  = (const float*)d_in[10];
    float* out = (float*)d_out;

    __nv_bfloat16 *ht, *qt, *kt, *v, *ot, *attn, *wq, *wk, *wv, *wp;
    cudaGetSymbolAddress((void**)&ht, g_ht);
    cudaGetSymbolAddress((void**)&qt, g_qt);
    cudaGetSymbolAddress((void**)&kt, g_kt);
    cudaGetSymbolAddress((void**)&v,  g_v);
    cudaGetSymbolAddress((void**)&ot, g_ot);
    cudaGetSymbolAddress((void**)&attn, g_attn);
    cudaGetSymbolAddress((void**)&wq, g_wq);
    cudaGetSymbolAddress((void**)&wk, g_wk);
    cudaGetSymbolAddress((void**)&wv, g_wv);
    cudaGetSymbolAddress((void**)&wp, g_wp);

    const int WN = CHN*CHN;
    cvt_kernel<<<WN/256, 256>>>(q_w, wq, WN);
    cvt_kernel<<<WN/256, 256>>>(k_w, wk, WN);
    cvt_kernel<<<WN/256, 256>>>(v_w, wv, WN);
    cvt_kernel<<<WN/256, 256>>>(p_w, wp, WN);

    gn_kernel<<<BATCH*GROUPS, 256>>>(x, gn_w, gn_b, ht);

    size_t sHN = (size_t)NPIX*CHN;   // per-batch elems of [n][c] / [c][n] tensors
    size_t sNN = (size_t)NPIX*NPIX;

    // q/k conv: C[m=c_out][n=pix] written transposed -> q^T [pix][c]
    dim3 cgrid(NPIX/BN, CHN/BM, BATCH);
    gemm_kernel<0><<<cgrid, 256>>>(wq, 0, ht, sHN, qt, sHN, q_b, nullptr, CHN, NPIX, CHN, 0.f);
    gemm_kernel<0><<<cgrid, 256>>>(wk, 0, ht, sHN, kt, sHN, k_b, nullptr, CHN, NPIX, CHN, 0.f);
    gemm_kernel<1><<<cgrid, 256>>>(wv, 0, ht, sHN, v,  sHN, v_b, nullptr, CHN, NPIX, CHN, 0.f);

    // logits: attn[i][j] = scale * sum_c q^T[i][c] k^T[j][c]
    dim3 lgrid(NPIX/BN, NPIX/BM, BATCH);
    gemm_kernel<2><<<lgrid, 256>>>(qt, sHN, kt, sHN, attn, sNN, nullptr, nullptr,
                                   NPIX, NPIX, CHN, 0.044194173824159216f);

    softmax_kernel<<<BATCH*NPIX, 256>>>(attn);

    // o[c][i] = sum_j v[c][j] attn[i][j] -> written transposed o^T [i][c]
    dim3 ogrid(NPIX/BN, CHN/BM, BATCH);
    gemm_kernel<3><<<ogrid, 256>>>(v, sHN, attn, sNN, ot, sHN, nullptr, nullptr,
                                   CHN, NPIX, NPIX, 0.f);

    // proj + bias + residual -> fp32 d_out
    gemm_kernel<4><<<cgrid, 256>>>(wp, 0, ot, sHN, out, sHN, p_b, x, CHN, NPIX, CHN, 0.f);
}

// round 4
// speedup vs baseline: 8.8255x; 1.4396x over previous
#include <cuda_runtime.h>
#include <cuda_bf16.h>
#include <cstdint>
#include <math.h>

#define BATCH 8
#define CHN 512
#define NPIX 4096
#define GROUPS 32
#define CPG 16

// ---------------- scratch (__device__ globals) -------------------------------
__device__ __nv_bfloat16 g_ht[(size_t)BATCH*NPIX*CHN];     // h^T  [b][i][c]
__device__ __nv_bfloat16 g_qt[(size_t)BATCH*NPIX*CHN];     // q^T  [b][i][c]
__device__ __nv_bfloat16 g_kt[(size_t)BATCH*NPIX*CHN];     // k^T  [b][j][c]
__device__ __nv_bfloat16 g_v [(size_t)BATCH*CHN*NPIX];     // v    [b][c][j]
__device__ __nv_bfloat16 g_ot[(size_t)BATCH*NPIX*CHN];     // o^T  [b][i][c]
__device__ __nv_bfloat16 g_attn[(size_t)BATCH*NPIX*NPIX];  // attn [b][i][j]
__device__ __nv_bfloat16 g_wq[CHN*CHN];
__device__ __nv_bfloat16 g_wk[CHN*CHN];
__device__ __nv_bfloat16 g_wv[CHN*CHN];
__device__ __nv_bfloat16 g_wp[CHN*CHN];

// ---------------- helpers ------------------------------------------------------
__device__ __forceinline__ uint32_t smem_u32(const void* p) {
    uint32_t a;
    asm("{ .reg .u64 t; cvta.to.shared.u64 t, %1; cvt.u32.u64 %0, t; }" : "=r"(a) : "l"(p));
    return a;
}
__device__ __forceinline__ void cpa16(uint32_t s, const void* g) {
    asm volatile("cp.async.cg.shared.global [%0], [%1], 16;" :: "r"(s), "l"(g) : "memory");
}
#define CPA_COMMIT() asm volatile("cp.async.commit_group;" ::: "memory")
#define CPA_WAIT2()  asm volatile("cp.async.wait_group 2;" ::: "memory")
#define CPA_WAIT0()  asm volatile("cp.async.wait_group 0;" ::: "memory")

__device__ __forceinline__ void ldsm4(uint32_t addr, uint32_t& r0, uint32_t& r1,
                                      uint32_t& r2, uint32_t& r3) {
    asm volatile("ldmatrix.sync.aligned.m8n8.x4.shared.b16 {%0,%1,%2,%3}, [%4];"
                 : "=r"(r0), "=r"(r1), "=r"(r2), "=r"(r3) : "r"(addr));
}

// ---------------- unified bf16 mma.sync GEMM ----------------------------------
// C[m][n] = scale * (sum_k A[m][k]*B[n][k]) + bias_m[m] + bias_n[n] (+resid, fp32)
#define BM 128
#define BN 128
#define BK 64
#define NSTAGE 3
#define ABYTES (BM*128)     // 16 KB (128 rows x 128B, SW128-xor swizzled)
#define STAGE_BYTES (2*ABYTES)
#define SMEM_TOTAL (NSTAGE*STAGE_BYTES)

__global__ void __launch_bounds__(256)
gemm_tc(const __nv_bfloat16* __restrict__ A, size_t strideA,
        const __nv_bfloat16* __restrict__ B, size_t strideB,
        void* __restrict__ Cv, size_t strideC, int ldC,
        const float* __restrict__ bias_m,
        const float* __restrict__ bias_n,
        const float* __restrict__ resid,
        float scale, int K, int out32) {
    extern __shared__ char smem[];
    uint32_t sb = smem_u32(smem);

    int tid  = threadIdx.x;
    int wid  = tid >> 5, lane = tid & 31;
    int wm = wid & 3;          // 4 warps on M: 32 rows each
    int wn = wid >> 2;         // 2 warps on N: 64 cols each
    int m0 = blockIdx.y * BM;
    int n0 = blockIdx.x * BN;
    const __nv_bfloat16* Ab = A + (size_t)blockIdx.z*strideA + (size_t)m0*K;
    const __nv_bfloat16* Bb = B + (size_t)blockIdx.z*strideB + (size_t)n0*K;

    float acc[2][8][4];
    #pragma unroll
    for (int i = 0; i < 2; i++)
        #pragma unroll
        for (int j = 0; j < 8; j++)
            #pragma unroll
            for (int r = 0; r < 4; r++) acc[i][j][r] = 0.f;

    // ---- tile copy: 1024 16B-chunks per operand, 4 per thread each ----
    auto copy_stage = [&](int s, int k0) {
        uint32_t ab = sb + s*STAGE_BYTES;
        uint32_t bbs = ab + ABYTES;
        #pragma unroll
        for (int i = 0; i < 4; i++) {
            int q = i*256 + tid;
            int r = q >> 3, c = q & 7;
            uint32_t off = r*128 + ((c ^ (r & 7)) << 4);
            cpa16(ab  + off, Ab + (size_t)r*K + k0 + c*8);
            cpa16(bbs + off, Bb + (size_t)r*K + k0 + c*8);
        }
        CPA_COMMIT();
    };

    int nt = K / BK;
    copy_stage(0, 0);
    copy_stage(1, BK);

    // precomputed ldmatrix row/chunk components
    int arow = wm*32 + (lane & 15);          // + am*16
    int akc  = lane >> 4;                    // 0/1 -> +8 k elems
    int brow = wn*64 + (lane & 7) + ((lane >> 4) << 3);   // + bt*16
    int bkc  = (lane >> 3) & 1;

    for (int it = 0; it < nt; it++) {
        if (it + 2 < nt) copy_stage((it + 2) % NSTAGE, (it + 2)*BK);
        if (it + 2 < nt) { CPA_WAIT2(); } else { CPA_WAIT0(); }
        __syncthreads();

        uint32_t as = sb + (it % NSTAGE)*STAGE_BYTES;
        uint32_t bs = as + ABYTES;

        #pragma unroll
        for (int ks = 0; ks < 4; ks++) {          // 4 x k16
            int kc = ks*2;
            uint32_t af[2][4];
            #pragma unroll
            for (int am = 0; am < 2; am++) {
                int r = arow + am*16;
                uint32_t addr = as + r*128 + (((kc + akc) ^ (r & 7)) << 4);
                ldsm4(addr, af[am][0], af[am][1], af[am][2], af[am][3]);
            }
            uint32_t bf[8][2];
            #pragma unroll
            for (int bt = 0; bt < 4; bt++) {
                int r = brow + bt*16;
                uint32_t addr = bs + r*128 + (((kc + bkc) ^ (r & 7)) << 4);
                ldsm4(addr, bf[bt*2][0], bf[bt*2][1], bf[bt*2+1][0], bf[bt*2+1][1]);
            }
            #pragma unroll
            for (int am = 0; am < 2; am++)
                #pragma unroll
                for (int an = 0; an < 8; an++) {
                    float* c = acc[am][an];
                    asm volatile(
                        "mma.sync.aligned.m16n8k16.row.col.f32.bf16.bf16.f32 "
                        "{%0,%1,%2,%3}, {%4,%5,%6,%7}, {%8,%9}, {%0,%1,%2,%3};"
                        : "+f"(c[0]), "+f"(c[1]), "+f"(c[2]), "+f"(c[3])
                        : "r"(af[am][0]), "r"(af[am][1]), "r"(af[am][2]), "r"(af[am][3]),
                          "r"(bf[an][0]), "r"(bf[an][1]));
                }
        }
        __syncthreads();
    }

    // ---- epilogue: all row-major, coalesced ----
    int g = lane >> 2, t = lane & 3;
    #pragma unroll
    for (int am = 0; am < 2; am++) {
        int ml = m0 + wm*32 + am*16 + g;
        int mh = ml + 8;
        float bml = bias_m ? bias_m[ml] : 0.f;
        float bmh = bias_m ? bias_m[mh] : 0.f;
        size_t rl = (size_t)blockIdx.z*strideC + (size_t)ml*ldC;
        size_t rh = (size_t)blockIdx.z*strideC + (size_t)mh*ldC;
        #pragma unroll
        for (int an = 0; an < 8; an++) {
            int ne = n0 + wn*64 + an*8 + 2*t;
            float v0 = acc[am][an][0]*scale + bml;
            float v1 = acc[am][an][1]*scale + bml;
            float v2 = acc[am][an][2]*scale + bmh;
            float v3 = acc[am][an][3]*scale + bmh;
            if (bias_n) {
                float b0 = __ldg(bias_n + ne), b1 = __ldg(bias_n + ne + 1);
                v0 += b0; v1 += b1; v2 += b0; v3 += b1;
            }
            if (!out32) {
                __nv_bfloat16* C = (__nv_bfloat16*)Cv;
                *reinterpret_cast<__nv_bfloat162*>(C + rl + ne) =
                    __nv_bfloat162{__float2bfloat16(v0), __float2bfloat16(v1)};
                *reinterpret_cast<__nv_bfloat162*>(C + rh + ne) =
                    __nv_bfloat162{__float2bfloat16(v2), __float2bfloat16(v3)};
            } else {
                float* C = (float*)Cv;
                float2 r0 = *reinterpret_cast<const float2*>(resid + rl + ne);
                float2 r1 = *reinterpret_cast<const float2*>(resid + rh + ne);
                *reinterpret_cast<float2*>(C + rl + ne) = float2{v0 + r0.x, v1 + r0.y};
                *reinterpret_cast<float2*>(C + rh + ne) = float2{v2 + r1.x, v3 + r1.y};
            }
        }
    }
}

// ---------------- fp32 -> bf16 weight convert --------------------------------
__global__ void cvt_kernel(const float* __restrict__ s, __nv_bfloat16* __restrict__ d, int n) {
    int i = blockIdx.x * blockDim.x + threadIdx.x;
    if (i < n) d[i] = __float2bfloat16(s[i]);
}

// ---------------- GroupNorm -> h^T bf16 [b][i][c] -----------------------------
__global__ void gn_kernel(const float* __restrict__ x,
                          const float* __restrict__ w,
                          const float* __restrict__ b,
                          __nv_bfloat16* __restrict__ ht) {
    int batch = blockIdx.x >> 5;
    int grp   = blockIdx.x & 31;
    const float* xp = x + ((size_t)batch*CHN + (size_t)grp*CPG) * NPIX;
    const int GE = CPG * NPIX;
    int tid = threadIdx.x;

    float s = 0.f, ss = 0.f;
    for (int i = tid; i < GE; i += 256) {
        float v = xp[i];
        s += v; ss += v*v;
    }
    __shared__ float r1[256], r2[256];
    r1[tid] = s; r2[tid] = ss;
    __syncthreads();
    for (int st = 128; st > 0; st >>= 1) {
        if (tid < st) { r1[tid] += r1[tid+st]; r2[tid] += r2[tid+st]; }
        __syncthreads();
    }
    float mean = r1[0] / (float)GE;
    float var  = r2[0] / (float)GE - mean*mean;
    float rstd = rsqrtf(var + 1e-6f);

    float wl[CPG], bl[CPG];
    #pragma unroll
    for (int c = 0; c < CPG; c++) { wl[c] = w[grp*CPG+c]; bl[c] = b[grp*CPG+c]; }

    for (int n = tid; n < NPIX; n += 256) {
        union { __nv_bfloat16 v[CPG]; uint4 u[2]; } pk;
        #pragma unroll
        for (int c = 0; c < CPG; c++) {
            float xv = xp[(size_t)c*NPIX + n];
            pk.v[c] = __float2bfloat16((xv - mean) * rstd * wl[c] + bl[c]);
        }
        uint4* dst = reinterpret_cast<uint4*>(ht + ((size_t)batch*NPIX + n)*CHN + grp*CPG);
        dst[0] = pk.u[0]; dst[1] = pk.u[1];
    }
}

// ---------------- row softmax, bf16 in-place ----------------------------------
__global__ void softmax_kernel(__nv_bfloat16* __restrict__ attn) {
    __nv_bfloat16* p = attn + (size_t)blockIdx.x * NPIX;
    __shared__ float buf[NPIX];
    __shared__ float red[8];
    int tid = threadIdx.x, lane = tid & 31, wid = tid >> 5;

    float mx = -1e30f;
    for (int i = tid; i < NPIX/8; i += 256) {
        uint4 raw = reinterpret_cast<const uint4*>(p)[i];
        const __nv_bfloat162* h2 = reinterpret_cast<const __nv_bfloat162*>(&raw);
        #pragma unroll
        for (int j = 0; j < 4; j++) {
            float2 f = __bfloat1622float2(h2[j]);
            buf[i*8 + 2*j]   = f.x;
            buf[i*8 + 2*j+1] = f.y;
            mx = fmaxf(mx, fmaxf(f.x, f.y));
        }
    }
    #pragma unroll
    for (int o = 16; o > 0; o >>= 1) mx = fmaxf(mx, __shfl_xor_sync(0xffffffffu, mx, o));
    if (lane == 0) red[wid] = mx;
    __syncthreads();
    if (tid == 0) {
        float m = red[0];
        #pragma unroll
        for (int i = 1; i < 8; i++) m = fmaxf(m, red[i]);
        red[0] = m;
    }
    __syncthreads();
    mx = red[0];
    __syncthreads();

    float s = 0.f;
    for (int i = tid; i < NPIX; i += 256) {
        float e = __expf(buf[i] - mx);
        buf[i] = e;
        s += e;
    }
    #pragma unroll
    for (int o = 16; o > 0; o >>= 1) s += __shfl_xor_sync(0xffffffffu, s, o);
    if (lane == 0) red[wid] = s;
    __syncthreads();
    if (tid == 0) {
        float m = 0.f;
        #pragma unroll
        for (int i = 0; i < 8; i++) m += red[i];
        red[0] = m;
    }
    __syncthreads();
    float inv = 1.0f / red[0];

    for (int i = tid; i < NPIX/8; i += 256) {
        uint4 raw;
        __nv_bfloat162* h2 = reinterpret_cast<__nv_bfloat162*>(&raw);
        #pragma unroll
        for (int j = 0; j < 4; j++) {
            h2[j] = __nv_bfloat162{__float2bfloat16(buf[i*8+2*j]   * inv),
                                   __float2bfloat16(buf[i*8+2*j+1] * inv)};
        }
        reinterpret_cast<uint4*>(p)[i] = raw;
    }
}

// ---------------- launch -------------------------------------------------------
extern "C" void kernel_launch(void* const* d_in, const int* in_sizes, int n_in,
                              void* d_out, int out_size) {
    const float* x    = (const float*)d_in[0];
    const float* gn_w = (const float*)d_in[1];
    const float* gn_b = (const float*)d_in[2];
    const float* q_w  = (const float*)d_in[3];
    const float* q_b  = (const float*)d_in[4];
    const float* k_w  = (const float*)d_in[5];
    const float* k_b  = (const float*)d_in[6];
    const float* v_w  = (const float*)d_in[7];
    const float* v_b  = (const float*)d_in[8];
    const float* p_w  = (const float*)d_in[9];
    const float* p_b  = (const float*)d_in[10];
    float* out = (float*)d_out;

    __nv_bfloat16 *ht, *qt, *kt, *v, *ot, *attn, *wq, *wk, *wv, *wp;
    cudaGetSymbolAddress((void**)&ht, g_ht);
    cudaGetSymbolAddress((void**)&qt, g_qt);
    cudaGetSymbolAddress((void**)&kt, g_kt);
    cudaGetSymbolAddress((void**)&v,  g_v);
    cudaGetSymbolAddress((void**)&ot, g_ot);
    cudaGetSymbolAddress((void**)&attn, g_attn);
    cudaGetSymbolAddress((void**)&wq, g_wq);
    cudaGetSymbolAddress((void**)&wk, g_wk);
    cudaGetSymbolAddress((void**)&wv, g_wv);
    cudaGetSymbolAddress((void**)&wp, g_wp);

    cudaFuncSetAttribute(gemm_tc, cudaFuncAttributeMaxDynamicSharedMemorySize, SMEM_TOTAL);

    const int WN = CHN*CHN;
    cvt_kernel<<<WN/256, 256>>>(q_w, wq, WN);
    cvt_kernel<<<WN/256, 256>>>(k_w, wk, WN);
    cvt_kernel<<<WN/256, 256>>>(v_w, wv, WN);
    cvt_kernel<<<WN/256, 256>>>(p_w, wp, WN);

    gn_kernel<<<BATCH*GROUPS, 256>>>(x, gn_w, gn_b, ht);

    size_t sHT = (size_t)NPIX*CHN;
    size_t sCN = (size_t)CHN*NPIX;
    size_t sNN = (size_t)NPIX*NPIX;

    // q^T[i][c] = sum_k ht[i][k] Wq[c][k] + qb[c]  (M=NPIX, N=CHN, K=CHN)
    dim3 qkgrid(CHN/BN, NPIX/BM, BATCH);
    gemm_tc<<<qkgrid, 256, SMEM_TOTAL>>>(ht, sHT, wq, 0, qt, sHT, CHN,
                                         nullptr, q_b, nullptr, 1.f, CHN, 0);
    gemm_tc<<<qkgrid, 256, SMEM_TOTAL>>>(ht, sHT, wk, 0, kt, sHT, CHN,
                                         nullptr, k_b, nullptr, 1.f, CHN, 0);
    // v[c][j] = sum_k Wv[c][k] ht[j][k] + vb[c]   (M=CHN, N=NPIX, K=CHN)
    dim3 vgrid(NPIX/BN, CHN/BM, BATCH);
    gemm_tc<<<vgrid, 256, SMEM_TOTAL>>>(wv, 0, ht, sHT, v, sCN, NPIX,
                                        v_b, nullptr, nullptr, 1.f, CHN, 0);
    // attn[i][j] = scale * sum_c q^T[i][c] k^T[j][c]  (M=N=NPIX, K=CHN)
    dim3 lgrid(NPIX/BN, NPIX/BM, BATCH);
    gemm_tc<<<lgrid, 256, SMEM_TOTAL>>>(qt, sHT, kt, sHT, attn, sNN, NPIX,
                                        nullptr, nullptr, nullptr,
                                        0.044194173824159216f, CHN, 0);

    softmax_kernel<<<BATCH*NPIX, 256>>>(attn);

    // o^T[i][c] = sum_j attn[i][j] v[c][j]  (M=NPIX, N=CHN, K=NPIX)
    dim3 ogrid(CHN/BN, NPIX/BM, BATCH);
    gemm_tc<<<ogrid, 256, SMEM_TOTAL>>>(attn, sNN, v, sCN, ot, sHT, CHN,
                                        nullptr, nullptr, nullptr, 1.f, NPIX, 0);

    // out[c][n] = sum_k Wp[c][k] o^T[n][k] + pb[c] + x  (fp32 + residual)
    dim3 pgrid(NPIX/BN, CHN/BM, BATCH);
    gemm_tc<<<pgrid, 256, SMEM_TOTAL>>>(wp, 0, ot, sHT, out, sCN, NPIX,
                                        p_b, nullptr, x, 1.f, CHN, 1);
}